// round 9
// baseline (speedup 1.0000x reference)
#include <cuda_runtime.h>
#include <math.h>
#include <stdint.h>

#define SEQ   128
#define BATCH 32
#define TB    4096      // SEQ*BATCH rows
#define HID   1024
#define VOC   32000
#define NBLK  128       // persistent grid size (<=148 -> fully co-resident)

// ---------------- scratch (device globals; no allocation allowed) -------------
__device__ float g_x [TB * HID];
__device__ float g_xw[TB * HID];
__device__ float g_y0[TB * HID];
__device__ float g_y1[TB * HID];
__device__ float g_hT[2 * BATCH * HID];   // ping-pong hidden, quad-k layout

__device__ unsigned g_bar_cnt;
__device__ volatile unsigned g_bar_flag;

__global__ void k_bar_reset() { g_bar_cnt = 0; g_bar_flag = 0; }

__device__ __forceinline__ void grid_sync(unsigned target_epoch) {
    __syncthreads();
    if (threadIdx.x == 0) {
        __threadfence();
        unsigned arrived = atomicAdd(&g_bar_cnt, 1u) + 1u;
        if (arrived == target_epoch * NBLK) {
            g_bar_flag = target_epoch;
        } else {
            while (g_bar_flag < target_epoch) { }
        }
        __threadfence();
    }
    __syncthreads();
}

__device__ __forceinline__ float tf32r(float x) {
    float y;
    asm("cvt.rna.tf32.f32 %0, %1;" : "=f"(y) : "f"(x));
    return y;
}

// ---------------- embedding gather -------------------------------------------
__global__ void k_gather(const int* __restrict__ idx, const float* __restrict__ emb,
                         float* __restrict__ out) {
    int r = blockIdx.x;
    int token = __ldg(&idx[r]);
    const float4* src = reinterpret_cast<const float4*>(emb + (size_t)token * HID);
    float4* dst = reinterpret_cast<float4*>(out + (size_t)r * HID);
    dst[threadIdx.x] = src[threadIdx.x];
}

// ---------------- TF32 tensor-core GEMM: C = A[M,K] @ B[N,K]^T + bias --------
// Block 128x128x32, 8 warps, warp tile 64x32 as 4x4 m16n8k8 mma.sync.
// Fragment-layout smem, 2-stage ping-pong (dynamic smem), one sync per k-tile.
#define BM 128
#define BN 128
#define BK 32
#define LPAD 33
#define ASZ (8  * 4 * LPAD * 4)    // floats per A stage
#define BSZ (16 * 4 * LPAD * 2)    // floats per B stage
#define GEMM_SMEM_BYTES ((2 * (ASZ + BSZ)) * 4)
__global__ __launch_bounds__(256)
void k_tf32gemm_bias(const float* __restrict__ A, const float* __restrict__ B,
                     const float* __restrict__ bias, float* __restrict__ C,
                     int M, int N, int K) {
    extern __shared__ float smemL[];
    float* Abuf = smemL;               // [2][ASZ]
    float* Bbuf = smemL + 2 * ASZ;     // [2][BSZ]
    const int bm = blockIdx.y * BM;
    const int bn = blockIdx.x * BN;
    const int tid  = threadIdx.x;
    const int wid  = tid >> 5;
    const int lane = tid & 31;
    const int wr = wid >> 2;
    const int wc = wid & 3;
    const int lr = lane >> 2;
    const int lc = lane & 3;

    // per-thread fill coordinates (4 float4 of A and B per k-tile)
    int frA[4], frB[4], rA[4], kkv[4];
    #pragma unroll
    for (int i = 0; i < 4; i++) {
        int s = tid + i * 256;
        int r = s >> 3;
        int kk = (s & 7) << 2;
        rA[i] = r; kkv[i] = kk;
        int ks = kk >> 3, ch = (kk >> 2) & 1;
        int mt = r >> 4, rr = r & 15;
        frA[i] = (((mt << 2) + ks) * LPAD + ((rr & 7) << 2)) * 4 + ((rr >> 3) | (ch << 1));
        int nt = r >> 3, nr = r & 7;
        frB[i] = (((nt << 2) + ks) * LPAD + (nr << 2)) * 2 + ch;
    }

    float acc[4][4][4];
    #pragma unroll
    for (int mi = 0; mi < 4; mi++)
        #pragma unroll
        for (int ni = 0; ni < 4; ni++)
            #pragma unroll
            for (int e = 0; e < 4; e++) acc[mi][ni][e] = 0.f;

    float4 pa[4], pb[4];
    #pragma unroll
    for (int i = 0; i < 4; i++) {
        pa[i] = *reinterpret_cast<const float4*>(&A[(size_t)(bm + rA[i]) * K + kkv[i]]);
        pb[i] = *reinterpret_cast<const float4*>(&B[(size_t)(bn + rA[i]) * K + kkv[i]]);
    }
    // prologue: stage 0 fill
    #pragma unroll
    for (int i = 0; i < 4; i++) {
        Abuf[frA[i] + 0]  = tf32r(pa[i].x);
        Abuf[frA[i] + 4]  = tf32r(pa[i].y);
        Abuf[frA[i] + 8]  = tf32r(pa[i].z);
        Abuf[frA[i] + 12] = tf32r(pa[i].w);
        Bbuf[frB[i] + 0]  = tf32r(pb[i].x);
        Bbuf[frB[i] + 2]  = tf32r(pb[i].y);
        Bbuf[frB[i] + 4]  = tf32r(pb[i].z);
        Bbuf[frB[i] + 6]  = tf32r(pb[i].w);
    }
    __syncthreads();

    const int ntiles = K / BK;
    for (int kt = 0; kt < ntiles; kt++) {
        const int cur = kt & 1;
        float* Ac = Abuf + cur * ASZ;
        float* Bc = Bbuf + cur * BSZ;
        const bool has_next = (kt + 1) < ntiles;
        if (has_next) {
            int k0 = (kt + 1) * BK;
            #pragma unroll
            for (int i = 0; i < 4; i++) {
                pa[i] = *reinterpret_cast<const float4*>(&A[(size_t)(bm + rA[i]) * K + k0 + kkv[i]]);
                pb[i] = *reinterpret_cast<const float4*>(&B[(size_t)(bn + rA[i]) * K + k0 + kkv[i]]);
            }
        }
        #pragma unroll
        for (int ks = 0; ks < 4; ks++) {
            float4 af[4]; float2 bf[4];
            #pragma unroll
            for (int mi = 0; mi < 4; mi++)
                af[mi] = *reinterpret_cast<const float4*>(
                    &Ac[((((wr << 2) + mi) * 4 + ks) * LPAD + lane) * 4]);
            #pragma unroll
            for (int ni = 0; ni < 4; ni++)
                bf[ni] = *reinterpret_cast<const float2*>(
                    &Bc[((((wc << 2) + ni) * 4 + ks) * LPAD + lane) * 2]);
            #pragma unroll
            for (int mi = 0; mi < 4; mi++)
                #pragma unroll
                for (int ni = 0; ni < 4; ni++) {
                    asm volatile(
                        "mma.sync.aligned.m16n8k8.row.col.f32.tf32.tf32.f32 "
                        "{%0,%1,%2,%3}, {%4,%5,%6,%7}, {%8,%9}, {%0,%1,%2,%3};"
                        : "+f"(acc[mi][ni][0]), "+f"(acc[mi][ni][1]),
                          "+f"(acc[mi][ni][2]), "+f"(acc[mi][ni][3])
                        : "r"(__float_as_uint(af[mi].x)), "r"(__float_as_uint(af[mi].y)),
                          "r"(__float_as_uint(af[mi].z)), "r"(__float_as_uint(af[mi].w)),
                          "r"(__float_as_uint(bf[ni].x)), "r"(__float_as_uint(bf[ni].y)));
                }
        }
        if (has_next) {
            float* An = Abuf + (cur ^ 1) * ASZ;
            float* Bn = Bbuf + (cur ^ 1) * BSZ;
            #pragma unroll
            for (int i = 0; i < 4; i++) {
                An[frA[i] + 0]  = tf32r(pa[i].x);
                An[frA[i] + 4]  = tf32r(pa[i].y);
                An[frA[i] + 8]  = tf32r(pa[i].z);
                An[frA[i] + 12] = tf32r(pa[i].w);
                Bn[frB[i] + 0]  = tf32r(pb[i].x);
                Bn[frB[i] + 2]  = tf32r(pb[i].y);
                Bn[frB[i] + 4]  = tf32r(pb[i].z);
                Bn[frB[i] + 6]  = tf32r(pb[i].w);
            }
        }
        __syncthreads();
    }

    #pragma unroll
    for (int mi = 0; mi < 4; mi++) {
        #pragma unroll
        for (int ni = 0; ni < 4; ni++) {
            int row = bm + wr * 64 + mi * 16 + lr;
            int col = bn + wc * 32 + ni * 8 + lc * 2;
            float b0 = __ldg(&bias[col]);
            float b1 = __ldg(&bias[col + 1]);
            float2 o0 = make_float2(acc[mi][ni][0] + b0, acc[mi][ni][1] + b1);
            float2 o1 = make_float2(acc[mi][ni][2] + b0, acc[mi][ni][3] + b1);
            *reinterpret_cast<float2*>(&C[(size_t)row * N + col]) = o0;
            *reinterpret_cast<float2*>(&C[(size_t)(row + 8) * N + col]) = o1;
        }
    }
}

// ---------------- hidden transpose: h[b][k] -> quad-k hq[k/4][b][k%4] ---------
__global__ void k_transpose_h(const float* __restrict__ h, float* __restrict__ hq) {
    int b = blockIdx.x;
    int k = threadIdx.x;
    hq[(k >> 2) * (BATCH * 4) + (b << 2) + (k & 3)] = h[b * HID + k];
}

// ---------------- persistent recurrence (one layer, 128 steps) ---------------
__global__ __launch_bounds__(256)
void k_rnn_persist(const float* __restrict__ xw,    // [SEQ][32][1024]
                   const float* __restrict__ Whh,   // [1024][1024]
                   const float* __restrict__ bhh,   // [1024]
                   float* __restrict__ hT,          // [2][1024*32] quad-k ping-pong
                   float* __restrict__ y,           // [SEQ][32][1024]
                   int epoch_base) {
    __shared__ float Ws[8][HID];
    __shared__ float red[8][8][32];
    __shared__ float bias_s[8];
    const int tid  = threadIdx.x;
    const int w    = tid >> 5;
    const int lane = tid & 31;
    const int j0   = blockIdx.x * 8;

    {
        const float4* src = reinterpret_cast<const float4*>(Whh + (size_t)j0 * HID);
        float4* dst = reinterpret_cast<float4*>(&Ws[0][0]);
        #pragma unroll
        for (int i = 0; i < 8; i++) dst[tid + 256 * i] = src[tid + 256 * i];
        if (tid < 8) bias_s[tid] = bhh[j0 + tid];
    }
    __syncthreads();

    const int kbase = w * 128;

    for (int t = 0; t < SEQ; t++) {
        const float* hp = hT + (size_t)(t & 1) * (HID * BATCH);
        float*       hn = hT + (size_t)((t + 1) & 1) * (HID * BATCH);

        float acc[8];
        #pragma unroll
        for (int j = 0; j < 8; j++) acc[j] = 0.f;

        #pragma unroll 4
        for (int kg = 0; kg < 128; kg += 8) {
            int q = (kbase + kg) >> 2;
            float4 h0 = __ldcg(reinterpret_cast<const float4*>(&hp[q * 128 + (lane << 2)]));
            float4 h1 = __ldcg(reinterpret_cast<const float4*>(&hp[(q + 1) * 128 + (lane << 2)]));
            #pragma unroll
            for (int j = 0; j < 8; j++) {
                float4 w0 = *reinterpret_cast<const float4*>(&Ws[j][kbase + kg]);
                float4 w1 = *reinterpret_cast<const float4*>(&Ws[j][kbase + kg + 4]);
                acc[j] += h0.x * w0.x + h0.y * w0.y + h0.z * w0.z + h0.w * w0.w
                        + h1.x * w1.x + h1.y * w1.y + h1.z * w1.z + h1.w * w1.w;
            }
        }

        #pragma unroll
        for (int j = 0; j < 8; j++) red[w][j][lane] = acc[j];
        __syncthreads();

        {
            const int j = tid >> 5, b = tid & 31;
            float s = red[0][j][b] + red[1][j][b] + red[2][j][b] + red[3][j][b]
                    + red[4][j][b] + red[5][j][b] + red[6][j][b] + red[7][j][b];
            s += __ldg(&xw[(size_t)t * (BATCH * HID) + b * HID + (j0 + j)]) + bias_s[j];
            float v = tanhf(s);
            int jj = j0 + j;
            hn[(jj >> 2) * 128 + (b << 2) + (jj & 3)] = v;
            y[(size_t)t * (BATCH * HID) + b * HID + jj] = v;
        }
        grid_sync((unsigned)(epoch_base + t + 1));
    }
}

// ---------------- in-place row log_softmax ------------------------------------
__global__ void k_logsoftmax(float* __restrict__ logits) {
    extern __shared__ float row[];
    __shared__ float red[33];
    const int tid = threadIdx.x;
    float* p = logits + (size_t)blockIdx.x * VOC;

    float mx = -INFINITY;
    for (int i = tid; i < VOC / 4; i += 256) {
        float4 v = reinterpret_cast<const float4*>(p)[i];
        reinterpret_cast<float4*>(row)[i] = v;
        mx = fmaxf(mx, fmaxf(fmaxf(v.x, v.y), fmaxf(v.z, v.w)));
    }
    #pragma unroll
    for (int o = 16; o; o >>= 1) mx = fmaxf(mx, __shfl_xor_sync(0xffffffffu, mx, o));
    if ((tid & 31) == 0) red[tid >> 5] = mx;
    __syncthreads();
    if (tid < 32) {
        float m = (tid < 8) ? red[tid] : -INFINITY;
        #pragma unroll
        for (int o = 4; o; o >>= 1) m = fmaxf(m, __shfl_xor_sync(0xffffffffu, m, o));
        if (tid == 0) red[32] = m;
    }
    __syncthreads();
    mx = red[32];

    float s = 0.f;
    for (int i = tid; i < VOC; i += 256) s += __expf(row[i] - mx);
    #pragma unroll
    for (int o = 16; o; o >>= 1) s += __shfl_xor_sync(0xffffffffu, s, o);
    if ((tid & 31) == 0) red[tid >> 5] = s;
    __syncthreads();
    if (tid < 32) {
        float t2 = (tid < 8) ? red[tid] : 0.f;
        #pragma unroll
        for (int o = 4; o; o >>= 1) t2 += __shfl_xor_sync(0xffffffffu, t2, o);
        if (tid == 0) red[32] = t2;
    }
    __syncthreads();
    float lse = mx + logf(red[32]);

    for (int i = tid; i < VOC / 4; i += 256) {
        float4 v = reinterpret_cast<float4*>(row)[i];
        float4 o = make_float4(v.x - lse, v.y - lse, v.z - lse, v.w - lse);
        reinterpret_cast<float4*>(p)[i] = o;
    }
}

// ---------------- final hidden copy -------------------------------------------
__global__ void k_copy_hidden(const float* __restrict__ y0, const float* __restrict__ y1,
                              float* __restrict__ outh) {
    int i = blockIdx.x * 256 + threadIdx.x;
    outh[i]               = y0[(SEQ - 1) * BATCH * HID + i];
    outh[BATCH * HID + i] = y1[(SEQ - 1) * BATCH * HID + i];
}

// ---------------- launch --------------------------------------------------------
extern "C" void kernel_launch(void* const* d_in, const int* in_sizes, int n_in,
                              void* d_out, int out_size) {
    const int*   input_x = (const int*)  d_in[0];
    const float* hidden  = (const float*)d_in[1];
    const float* emb     = (const float*)d_in[2];
    const float* W_ih    = (const float*)d_in[3];
    const float* W_hh    = (const float*)d_in[4];
    const float* b_ih    = (const float*)d_in[5];
    const float* b_hh    = (const float*)d_in[6];
    const float* W_out   = (const float*)d_in[7];
    const float* b_out   = (const float*)d_in[8];
    float* out = (float*)d_out;

    static float *x = nullptr, *xw, *y0, *y1, *hT;
    if (!x) {
        cudaGetSymbolAddress((void**)&x,  g_x);
        cudaGetSymbolAddress((void**)&xw, g_xw);
        cudaGetSymbolAddress((void**)&y0, g_y0);
        cudaGetSymbolAddress((void**)&y1, g_y1);
        cudaGetSymbolAddress((void**)&hT, g_hT);
        cudaFuncSetAttribute(k_logsoftmax,
                             cudaFuncAttributeMaxDynamicSharedMemorySize, VOC * 4);
        cudaFuncSetAttribute(k_tf32gemm_bias,
                             cudaFuncAttributeMaxDynamicSharedMemorySize, GEMM_SMEM_BYTES);
    }

    dim3 gsmall(HID / BN, TB / BM);   // (8, 32)
    dim3 gbig(VOC / BN, TB / BM);     // (250, 32)

    // launch order arranged so launch #4 (profiled) is the tf32 GEMM
    k_bar_reset<<<1, 1>>>();                                         // 1
    k_gather<<<TB, 256>>>(input_x, emb, x);                          // 2
    k_transpose_h<<<BATCH, HID>>>(hidden, hT);                       // 3  (layer 0)
    k_tf32gemm_bias<<<gsmall, 256, GEMM_SMEM_BYTES>>>(               // 4  <- profiled
        x, W_ih, b_ih, xw, TB, HID, HID);
    k_rnn_persist<<<NBLK, 256>>>(xw, W_hh, b_hh, hT, y0, 0);         // 5

    k_tf32gemm_bias<<<gsmall, 256, GEMM_SMEM_BYTES>>>(               // 6
        y0, W_ih + (size_t)HID * HID, b_ih + HID, xw, TB, HID, HID);
    k_transpose_h<<<BATCH, HID>>>(hidden + BATCH * HID, hT);         // 7  (layer 1)
    k_rnn_persist<<<NBLK, 256>>>(xw, W_hh + (size_t)HID * HID,       // 8
                                 b_hh + HID, hT, y1, SEQ);

    k_tf32gemm_bias<<<gbig, 256, GEMM_SMEM_BYTES>>>(                 // 9
        y1, W_out, b_out, out, TB, VOC, HID);
    k_logsoftmax<<<TB, 256, VOC * 4>>>(out);                         // 10

    long long hid_off = (long long)TB * VOC;
    if ((long long)out_size >= hid_off + 2LL * BATCH * HID) {
        k_copy_hidden<<<BATCH * HID / 256, 256>>>(y0, y1, out + hid_off);  // 11
    }
}

// round 11
// speedup vs baseline: 1.1505x; 1.1505x over previous
#include <cuda_runtime.h>
#include <math.h>
#include <stdint.h>

#define SEQ   128
#define BATCH 32
#define TB    4096      // SEQ*BATCH rows
#define HID   1024
#define VOC   32000
#define NBLK  128       // persistent grid size (<=148 -> fully co-resident)

// ---------------- scratch (device globals; no allocation allowed) -------------
__device__ float g_x [TB * HID];
__device__ float g_xw[TB * HID];
__device__ float g_y0[TB * HID];
__device__ float g_y1[TB * HID];
__device__ float g_hT[2 * BATCH * HID];   // ping-pong hidden, quad-k layout

__device__ unsigned g_bar_cnt;
__device__ volatile unsigned g_bar_flag;

__global__ void k_bar_reset() { g_bar_cnt = 0; g_bar_flag = 0; }

__device__ __forceinline__ void grid_sync(unsigned target_epoch) {
    __syncthreads();
    if (threadIdx.x == 0) {
        __threadfence();
        unsigned arrived = atomicAdd(&g_bar_cnt, 1u) + 1u;
        if (arrived == target_epoch * NBLK) {
            g_bar_flag = target_epoch;
        } else {
            while (g_bar_flag < target_epoch) { }
        }
        __threadfence();
    }
    __syncthreads();
}

__device__ __forceinline__ float tf32r(float x) {
    float y;
    asm("cvt.rna.tf32.f32 %0, %1;" : "=f"(y) : "f"(x));
    return y;
}

// ---------------- embedding gather -------------------------------------------
__global__ void k_gather(const int* __restrict__ idx, const float* __restrict__ emb,
                         float* __restrict__ out) {
    int r = blockIdx.x;
    int token = __ldg(&idx[r]);
    const float4* src = reinterpret_cast<const float4*>(emb + (size_t)token * HID);
    float4* dst = reinterpret_cast<float4*>(out + (size_t)r * HID);
    dst[threadIdx.x] = src[threadIdx.x];
}

// ---------------- TF32 tensor-core GEMM: C = A[M,K] @ B[N,K]^T + bias --------
// Block 128x256x32, 16 warps (warp grid 2x8), warp tile 64x32 (4x4 m16n8k8).
// Fragment-layout smem (vector LDS), single stage + register prefetch (R8 flow).
#define BM 128
#define BN 256
#define BK 32
#define LPAD 33
#define ASZ (8  * 4 * LPAD * 4)    // A stage floats  (128 rows)
#define BSZ (32 * 4 * LPAD * 2)    // B stage floats  (256 rows)
#define GEMM_SMEM_BYTES ((ASZ + BSZ) * 4)
__global__ __launch_bounds__(512, 1)
void k_tf32gemm_bias(const float* __restrict__ A, const float* __restrict__ B,
                     const float* __restrict__ bias, float* __restrict__ C,
                     int M, int N, int K) {
    extern __shared__ float smemL[];
    float* AsF = smemL;            // [mt 0..7][ks 0..3][lane pad][e 0..3]
    float* BsF = smemL + ASZ;      // [nt 0..31][ks][lane pad][e 0..1]
    const int bm = blockIdx.y * BM;
    const int bn = blockIdx.x * BN;
    const int tid  = threadIdx.x;
    const int wid  = tid >> 5;
    const int lane = tid & 31;
    const int wr = wid & 1;            // warp row: 2 x 64 rows
    const int wc = wid >> 1;           // warp col: 8 x 32 cols
    const int lr = lane >> 2;
    const int lc = lane & 3;

    // fill coordinates: A = 1024 float4 (2/thread), B = 2048 float4 (4/thread)
    int frA[2], rAa[2];
    int frB[4], rBb[4];
    int kkA[2], kkB[4];
    #pragma unroll
    for (int i = 0; i < 2; i++) {
        int s = tid + i * 512;
        int r = s >> 3;                 // 0..127
        int kk = (s & 7) << 2;
        rAa[i] = r; kkA[i] = kk;
        int ks = kk >> 3, ch = (kk >> 2) & 1;
        int mt = r >> 4, rr = r & 15;
        frA[i] = (((mt << 2) + ks) * LPAD + ((rr & 7) << 2)) * 4 + ((rr >> 3) | (ch << 1));
    }
    #pragma unroll
    for (int i = 0; i < 4; i++) {
        int s = tid + i * 512;
        int r = s >> 3;                 // 0..255
        int kk = (s & 7) << 2;
        rBb[i] = r; kkB[i] = kk;
        int ks = kk >> 3, ch = (kk >> 2) & 1;
        int nt = r >> 3, nr = r & 7;
        frB[i] = (((nt << 2) + ks) * LPAD + (nr << 2)) * 2 + ch;
    }

    float acc[4][4][4];
    #pragma unroll
    for (int mi = 0; mi < 4; mi++)
        #pragma unroll
        for (int ni = 0; ni < 4; ni++)
            #pragma unroll
            for (int e = 0; e < 4; e++) acc[mi][ni][e] = 0.f;

    float4 pa[2], pb[4];
    #pragma unroll
    for (int i = 0; i < 2; i++)
        pa[i] = *reinterpret_cast<const float4*>(&A[(size_t)(bm + rAa[i]) * K + kkA[i]]);
    #pragma unroll
    for (int i = 0; i < 4; i++)
        pb[i] = *reinterpret_cast<const float4*>(&B[(size_t)(bn + rBb[i]) * K + kkB[i]]);

    for (int k0 = 0; k0 < K; k0 += BK) {
        #pragma unroll
        for (int i = 0; i < 2; i++) {
            AsF[frA[i] + 0]  = tf32r(pa[i].x);
            AsF[frA[i] + 4]  = tf32r(pa[i].y);
            AsF[frA[i] + 8]  = tf32r(pa[i].z);
            AsF[frA[i] + 12] = tf32r(pa[i].w);
        }
        #pragma unroll
        for (int i = 0; i < 4; i++) {
            BsF[frB[i] + 0]  = tf32r(pb[i].x);
            BsF[frB[i] + 2]  = tf32r(pb[i].y);
            BsF[frB[i] + 4]  = tf32r(pb[i].z);
            BsF[frB[i] + 6]  = tf32r(pb[i].w);
        }
        __syncthreads();
        if (k0 + BK < K) {             // prefetch next tile; hidden under MMA
            #pragma unroll
            for (int i = 0; i < 2; i++)
                pa[i] = *reinterpret_cast<const float4*>(
                            &A[(size_t)(bm + rAa[i]) * K + k0 + BK + kkA[i]]);
            #pragma unroll
            for (int i = 0; i < 4; i++)
                pb[i] = *reinterpret_cast<const float4*>(
                            &B[(size_t)(bn + rBb[i]) * K + k0 + BK + kkB[i]]);
        }
        #pragma unroll
        for (int ks = 0; ks < 4; ks++) {
            float4 af[4]; float2 bf[4];
            #pragma unroll
            for (int mi = 0; mi < 4; mi++)
                af[mi] = *reinterpret_cast<const float4*>(
                    &AsF[((((wr << 2) + mi) * 4 + ks) * LPAD + lane) * 4]);
            #pragma unroll
            for (int ni = 0; ni < 4; ni++)
                bf[ni] = *reinterpret_cast<const float2*>(
                    &BsF[((((wc << 2) + ni) * 4 + ks) * LPAD + lane) * 2]);
            #pragma unroll
            for (int mi = 0; mi < 4; mi++)
                #pragma unroll
                for (int ni = 0; ni < 4; ni++) {
                    asm volatile(
                        "mma.sync.aligned.m16n8k8.row.col.f32.tf32.tf32.f32 "
                        "{%0,%1,%2,%3}, {%4,%5,%6,%7}, {%8,%9}, {%0,%1,%2,%3};"
                        : "+f"(acc[mi][ni][0]), "+f"(acc[mi][ni][1]),
                          "+f"(acc[mi][ni][2]), "+f"(acc[mi][ni][3])
                        : "r"(__float_as_uint(af[mi].x)), "r"(__float_as_uint(af[mi].y)),
                          "r"(__float_as_uint(af[mi].z)), "r"(__float_as_uint(af[mi].w)),
                          "r"(__float_as_uint(bf[ni].x)), "r"(__float_as_uint(bf[ni].y)));
                }
        }
        __syncthreads();
    }

    #pragma unroll
    for (int mi = 0; mi < 4; mi++) {
        #pragma unroll
        for (int ni = 0; ni < 4; ni++) {
            int row = bm + wr * 64 + mi * 16 + lr;
            int col = bn + wc * 32 + ni * 8 + lc * 2;
            float b0 = __ldg(&bias[col]);
            float b1 = __ldg(&bias[col + 1]);
            float2 o0 = make_float2(acc[mi][ni][0] + b0, acc[mi][ni][1] + b1);
            float2 o1 = make_float2(acc[mi][ni][2] + b0, acc[mi][ni][3] + b1);
            *reinterpret_cast<float2*>(&C[(size_t)row * N + col]) = o0;
            *reinterpret_cast<float2*>(&C[(size_t)(row + 8) * N + col]) = o1;
        }
    }
}

// ---------------- hidden transpose: h[b][k] -> quad-k hq[k/4][b][k%4] ---------
__global__ void k_transpose_h(const float* __restrict__ h, float* __restrict__ hq) {
    int b = blockIdx.x;
    int k = threadIdx.x;
    hq[(k >> 2) * (BATCH * 4) + (b << 2) + (k & 3)] = h[b * HID + k];
}

// ---------------- persistent recurrence (one layer, 128 steps) ---------------
__global__ __launch_bounds__(256)
void k_rnn_persist(const float* __restrict__ xw,    // [SEQ][32][1024]
                   const float* __restrict__ Whh,   // [1024][1024]
                   const float* __restrict__ bhh,   // [1024]
                   float* __restrict__ hT,          // [2][1024*32] quad-k ping-pong
                   float* __restrict__ y,           // [SEQ][32][1024]
                   int epoch_base) {
    __shared__ float Ws[8][HID];
    __shared__ float red[8][8][32];
    __shared__ float bias_s[8];
    const int tid  = threadIdx.x;
    const int w    = tid >> 5;
    const int lane = tid & 31;
    const int j0   = blockIdx.x * 8;

    {
        const float4* src = reinterpret_cast<const float4*>(Whh + (size_t)j0 * HID);
        float4* dst = reinterpret_cast<float4*>(&Ws[0][0]);
        #pragma unroll
        for (int i = 0; i < 8; i++) dst[tid + 256 * i] = src[tid + 256 * i];
        if (tid < 8) bias_s[tid] = bhh[j0 + tid];
    }
    __syncthreads();

    const int kbase = w * 128;

    for (int t = 0; t < SEQ; t++) {
        const float* hp = hT + (size_t)(t & 1) * (HID * BATCH);
        float*       hn = hT + (size_t)((t + 1) & 1) * (HID * BATCH);

        float acc[8];
        #pragma unroll
        for (int j = 0; j < 8; j++) acc[j] = 0.f;

        #pragma unroll 4
        for (int kg = 0; kg < 128; kg += 8) {
            int q = (kbase + kg) >> 2;
            float4 h0 = __ldcg(reinterpret_cast<const float4*>(&hp[q * 128 + (lane << 2)]));
            float4 h1 = __ldcg(reinterpret_cast<const float4*>(&hp[(q + 1) * 128 + (lane << 2)]));
            #pragma unroll
            for (int j = 0; j < 8; j++) {
                float4 w0 = *reinterpret_cast<const float4*>(&Ws[j][kbase + kg]);
                float4 w1 = *reinterpret_cast<const float4*>(&Ws[j][kbase + kg + 4]);
                acc[j] += h0.x * w0.x + h0.y * w0.y + h0.z * w0.z + h0.w * w0.w
                        + h1.x * w1.x + h1.y * w1.y + h1.z * w1.z + h1.w * w1.w;
            }
        }

        #pragma unroll
        for (int j = 0; j < 8; j++) red[w][j][lane] = acc[j];
        __syncthreads();

        {
            const int j = tid >> 5, b = tid & 31;
            float s = red[0][j][b] + red[1][j][b] + red[2][j][b] + red[3][j][b]
                    + red[4][j][b] + red[5][j][b] + red[6][j][b] + red[7][j][b];
            s += __ldg(&xw[(size_t)t * (BATCH * HID) + b * HID + (j0 + j)]) + bias_s[j];
            float v = tanhf(s);
            int jj = j0 + j;
            hn[(jj >> 2) * 128 + (b << 2) + (jj & 3)] = v;
            y[(size_t)t * (BATCH * HID) + b * HID + jj] = v;
        }
        grid_sync((unsigned)(epoch_base + t + 1));
    }
}

// ---------------- in-place row log_softmax ------------------------------------
__global__ void k_logsoftmax(float* __restrict__ logits) {
    extern __shared__ float row[];
    __shared__ float red[33];
    const int tid = threadIdx.x;
    float* p = logits + (size_t)blockIdx.x * VOC;

    float mx = -INFINITY;
    for (int i = tid; i < VOC / 4; i += 256) {
        float4 v = reinterpret_cast<const float4*>(p)[i];
        reinterpret_cast<float4*>(row)[i] = v;
        mx = fmaxf(mx, fmaxf(fmaxf(v.x, v.y), fmaxf(v.z, v.w)));
    }
    #pragma unroll
    for (int o = 16; o; o >>= 1) mx = fmaxf(mx, __shfl_xor_sync(0xffffffffu, mx, o));
    if ((tid & 31) == 0) red[tid >> 5] = mx;
    __syncthreads();
    if (tid < 32) {
        float m = (tid < 8) ? red[tid] : -INFINITY;
        #pragma unroll
        for (int o = 4; o; o >>= 1) m = fmaxf(m, __shfl_xor_sync(0xffffffffu, m, o));
        if (tid == 0) red[32] = m;
    }
    __syncthreads();
    mx = red[32];

    float s = 0.f;
    for (int i = tid; i < VOC; i += 256) s += __expf(row[i] - mx);
    #pragma unroll
    for (int o = 16; o; o >>= 1) s += __shfl_xor_sync(0xffffffffu, s, o);
    if ((tid & 31) == 0) red[tid >> 5] = s;
    __syncthreads();
    if (tid < 32) {
        float t2 = (tid < 8) ? red[tid] : 0.f;
        #pragma unroll
        for (int o = 4; o; o >>= 1) t2 += __shfl_xor_sync(0xffffffffu, t2, o);
        if (tid == 0) red[32] = t2;
    }
    __syncthreads();
    float lse = mx + logf(red[32]);

    for (int i = tid; i < VOC / 4; i += 256) {
        float4 v = reinterpret_cast<float4*>(row)[i];
        float4 o = make_float4(v.x - lse, v.y - lse, v.z - lse, v.w - lse);
        reinterpret_cast<float4*>(p)[i] = o;
    }
}

// ---------------- final hidden copy -------------------------------------------
__global__ void k_copy_hidden(const float* __restrict__ y0, const float* __restrict__ y1,
                              float* __restrict__ outh) {
    int i = blockIdx.x * 256 + threadIdx.x;
    outh[i]               = y0[(SEQ - 1) * BATCH * HID + i];
    outh[BATCH * HID + i] = y1[(SEQ - 1) * BATCH * HID + i];
}

// ---------------- launch --------------------------------------------------------
extern "C" void kernel_launch(void* const* d_in, const int* in_sizes, int n_in,
                              void* d_out, int out_size) {
    const int*   input_x = (const int*)  d_in[0];
    const float* hidden  = (const float*)d_in[1];
    const float* emb     = (const float*)d_in[2];
    const float* W_ih    = (const float*)d_in[3];
    const float* W_hh    = (const float*)d_in[4];
    const float* b_ih    = (const float*)d_in[5];
    const float* b_hh    = (const float*)d_in[6];
    const float* W_out   = (const float*)d_in[7];
    const float* b_out   = (const float*)d_in[8];
    float* out = (float*)d_out;

    static float *x = nullptr, *xw, *y0, *y1, *hT;
    if (!x) {
        cudaGetSymbolAddress((void**)&x,  g_x);
        cudaGetSymbolAddress((void**)&xw, g_xw);
        cudaGetSymbolAddress((void**)&y0, g_y0);
        cudaGetSymbolAddress((void**)&y1, g_y1);
        cudaGetSymbolAddress((void**)&hT, g_hT);
        cudaFuncSetAttribute(k_logsoftmax,
                             cudaFuncAttributeMaxDynamicSharedMemorySize, VOC * 4);
        cudaFuncSetAttribute(k_tf32gemm_bias,
                             cudaFuncAttributeMaxDynamicSharedMemorySize, GEMM_SMEM_BYTES);
    }

    dim3 gsmall(HID / BN, TB / BM);   // (4, 32)
    dim3 gbig(VOC / BN, TB / BM);     // (125, 32)

    // launch order arranged so launch #4 (profiled) is the tf32 GEMM
    k_bar_reset<<<1, 1>>>();                                         // 1
    k_gather<<<TB, 256>>>(input_x, emb, x);                          // 2
    k_transpose_h<<<BATCH, HID>>>(hidden, hT);                       // 3  (layer 0)
    k_tf32gemm_bias<<<gsmall, 512, GEMM_SMEM_BYTES>>>(               // 4  <- profiled
        x, W_ih, b_ih, xw, TB, HID, HID);
    k_rnn_persist<<<NBLK, 256>>>(xw, W_hh, b_hh, hT, y0, 0);         // 5

    k_tf32gemm_bias<<<gsmall, 512, GEMM_SMEM_BYTES>>>(               // 6
        y0, W_ih + (size_t)HID * HID, b_ih + HID, xw, TB, HID, HID);
    k_transpose_h<<<BATCH, HID>>>(hidden + BATCH * HID, hT);         // 7  (layer 1)
    k_rnn_persist<<<NBLK, 256>>>(xw, W_hh + (size_t)HID * HID,       // 8
                                 b_hh + HID, hT, y1, SEQ);

    k_tf32gemm_bias<<<gbig, 512, GEMM_SMEM_BYTES>>>(                 // 9
        y1, W_out, b_out, out, TB, VOC, HID);
    k_logsoftmax<<<TB, 256, VOC * 4>>>(out);                         // 10

    long long hid_off = (long long)TB * VOC;
    if ((long long)out_size >= hid_off + 2LL * BATCH * HID) {
        k_copy_hidden<<<BATCH * HID / 256, 256>>>(y0, y1, out + hid_off);  // 11
    }
}

// round 15
// speedup vs baseline: 1.1645x; 1.0121x over previous
#include <cuda_runtime.h>
#include <math.h>
#include <stdint.h>

#define SEQ   128
#define BATCH 32
#define TB    4096      // SEQ*BATCH rows
#define HID   1024
#define VOC   32000
#define NBLK  128       // persistent grid size (<=148 -> fully co-resident)

// ---------------- scratch (device globals; no allocation allowed) -------------
__device__ float g_x [TB * HID];
__device__ float g_xw[TB * HID];
__device__ float g_y0[TB * HID];
__device__ float g_y1[TB * HID];
__device__ float g_hT[2 * BATCH * HID];   // ping-pong hidden, quad-k layout

__device__ unsigned g_bar_cnt;
__device__ volatile unsigned g_bar_flag;

__global__ void k_bar_reset() { g_bar_cnt = 0; g_bar_flag = 0; }

__device__ __forceinline__ void grid_sync(unsigned target_epoch) {
    __syncthreads();
    if (threadIdx.x == 0) {
        __threadfence();
        unsigned arrived = atomicAdd(&g_bar_cnt, 1u) + 1u;
        if (arrived == target_epoch * NBLK) {
            g_bar_flag = target_epoch;
        } else {
            while (g_bar_flag < target_epoch) { }
        }
        __threadfence();
    }
    __syncthreads();
}

__device__ __forceinline__ float tf32r(float x) {
    float y;
    asm("cvt.rna.tf32.f32 %0, %1;" : "=f"(y) : "f"(x));
    return y;
}

// packed fp32x2 FMA (base sm_100+ PTX; NOT an 'a'-gated feature)
#define FMA2(acc, a, b) \
    asm("fma.rn.f32x2 %0, %1, %2, %0;" : "+l"(acc) : "l"(a), "l"(b))

// ---------------- embedding gather -------------------------------------------
__global__ void k_gather(const int* __restrict__ idx, const float* __restrict__ emb,
                         float* __restrict__ out) {
    int r = blockIdx.x;
    int token = __ldg(&idx[r]);
    const float4* src = reinterpret_cast<const float4*>(emb + (size_t)token * HID);
    float4* dst = reinterpret_cast<float4*>(out + (size_t)r * HID);
    dst[threadIdx.x] = src[threadIdx.x];
}

// ---------------- TF32 tensor-core GEMM: C = A[M,K] @ B[N,K]^T + bias --------
// Block 128x256x32, 16 warps (warp grid 2x8), warp tile 64x32 (4x4 m16n8k8).
// Fragment-layout smem (vector LDS), single stage + register prefetch.
#define BM 128
#define BN 256
#define BK 32
#define LPAD 33
#define ASZ (8  * 4 * LPAD * 4)    // A stage floats  (128 rows)
#define BSZ (32 * 4 * LPAD * 2)    // B stage floats  (256 rows)
#define GEMM_SMEM_BYTES ((ASZ + BSZ) * 4)
__global__ __launch_bounds__(512, 1)
void k_tf32gemm_bias(const float* __restrict__ A, const float* __restrict__ B,
                     const float* __restrict__ bias, float* __restrict__ C,
                     int M, int N, int K) {
    extern __shared__ float smemL[];
    float* AsF = smemL;            // [mt 0..7][ks 0..3][lane pad][e 0..3]
    float* BsF = smemL + ASZ;      // [nt 0..31][ks][lane pad][e 0..1]
    const int bm = blockIdx.y * BM;
    const int bn = blockIdx.x * BN;
    const int tid  = threadIdx.x;
    const int wid  = tid >> 5;
    const int lane = tid & 31;
    const int wr = wid & 1;            // warp row: 2 x 64 rows
    const int wc = wid >> 1;           // warp col: 8 x 32 cols
    const int lr = lane >> 2;
    const int lc = lane & 3;

    int frA[2], rAa[2];
    int frB[4], rBb[4];
    int kkA[2], kkB[4];
    #pragma unroll
    for (int i = 0; i < 2; i++) {
        int s = tid + i * 512;
        int r = s >> 3;
        int kk = (s & 7) << 2;
        rAa[i] = r; kkA[i] = kk;
        int ks = kk >> 3, ch = (kk >> 2) & 1;
        int mt = r >> 4, rr = r & 15;
        frA[i] = (((mt << 2) + ks) * LPAD + ((rr & 7) << 2)) * 4 + ((rr >> 3) | (ch << 1));
    }
    #pragma unroll
    for (int i = 0; i < 4; i++) {
        int s = tid + i * 512;
        int r = s >> 3;
        int kk = (s & 7) << 2;
        rBb[i] = r; kkB[i] = kk;
        int ks = kk >> 3, ch = (kk >> 2) & 1;
        int nt = r >> 3, nr = r & 7;
        frB[i] = (((nt << 2) + ks) * LPAD + (nr << 2)) * 2 + ch;
    }

    float acc[4][4][4];
    #pragma unroll
    for (int mi = 0; mi < 4; mi++)
        #pragma unroll
        for (int ni = 0; ni < 4; ni++)
            #pragma unroll
            for (int e = 0; e < 4; e++) acc[mi][ni][e] = 0.f;

    float4 pa[2], pb[4];
    #pragma unroll
    for (int i = 0; i < 2; i++)
        pa[i] = *reinterpret_cast<const float4*>(&A[(size_t)(bm + rAa[i]) * K + kkA[i]]);
    #pragma unroll
    for (int i = 0; i < 4; i++)
        pb[i] = *reinterpret_cast<const float4*>(&B[(size_t)(bn + rBb[i]) * K + kkB[i]]);

    for (int k0 = 0; k0 < K; k0 += BK) {
        #pragma unroll
        for (int i = 0; i < 2; i++) {
            AsF[frA[i] + 0]  = tf32r(pa[i].x);
            AsF[frA[i] + 4]  = tf32r(pa[i].y);
            AsF[frA[i] + 8]  = tf32r(pa[i].z);
            AsF[frA[i] + 12] = tf32r(pa[i].w);
        }
        #pragma unroll
        for (int i = 0; i < 4; i++) {
            BsF[frB[i] + 0]  = tf32r(pb[i].x);
            BsF[frB[i] + 2]  = tf32r(pb[i].y);
            BsF[frB[i] + 4]  = tf32r(pb[i].z);
            BsF[frB[i] + 6]  = tf32r(pb[i].w);
        }
        __syncthreads();
        if (k0 + BK < K) {
            #pragma unroll
            for (int i = 0; i < 2; i++)
                pa[i] = *reinterpret_cast<const float4*>(
                            &A[(size_t)(bm + rAa[i]) * K + k0 + BK + kkA[i]]);
            #pragma unroll
            for (int i = 0; i < 4; i++)
                pb[i] = *reinterpret_cast<const float4*>(
                            &B[(size_t)(bn + rBb[i]) * K + k0 + BK + kkB[i]]);
        }
        #pragma unroll
        for (int ks = 0; ks < 4; ks++) {
            float4 af[4]; float2 bf[4];
            #pragma unroll
            for (int mi = 0; mi < 4; mi++)
                af[mi] = *reinterpret_cast<const float4*>(
                    &AsF[((((wr << 2) + mi) * 4 + ks) * LPAD + lane) * 4]);
            #pragma unroll
            for (int ni = 0; ni < 4; ni++)
                bf[ni] = *reinterpret_cast<const float2*>(
                    &BsF[((((wc << 2) + ni) * 4 + ks) * LPAD + lane) * 2]);
            #pragma unroll
            for (int mi = 0; mi < 4; mi++)
                #pragma unroll
                for (int ni = 0; ni < 4; ni++) {
                    asm volatile(
                        "mma.sync.aligned.m16n8k8.row.col.f32.tf32.tf32.f32 "
                        "{%0,%1,%2,%3}, {%4,%5,%6,%7}, {%8,%9}, {%0,%1,%2,%3};"
                        : "+f"(acc[mi][ni][0]), "+f"(acc[mi][ni][1]),
                          "+f"(acc[mi][ni][2]), "+f"(acc[mi][ni][3])
                        : "r"(__float_as_uint(af[mi].x)), "r"(__float_as_uint(af[mi].y)),
                          "r"(__float_as_uint(af[mi].z)), "r"(__float_as_uint(af[mi].w)),
                          "r"(__float_as_uint(bf[ni].x)), "r"(__float_as_uint(bf[ni].y)));
                }
        }
        __syncthreads();
    }

    #pragma unroll
    for (int mi = 0; mi < 4; mi++) {
        #pragma unroll
        for (int ni = 0; ni < 4; ni++) {
            int row = bm + wr * 64 + mi * 16 + lr;
            int col = bn + wc * 32 + ni * 8 + lc * 2;
            float b0 = __ldg(&bias[col]);
            float b1 = __ldg(&bias[col + 1]);
            float2 o0 = make_float2(acc[mi][ni][0] + b0, acc[mi][ni][1] + b1);
            float2 o1 = make_float2(acc[mi][ni][2] + b0, acc[mi][ni][3] + b1);
            *reinterpret_cast<float2*>(&C[(size_t)row * N + col]) = o0;
            *reinterpret_cast<float2*>(&C[(size_t)(row + 8) * N + col]) = o1;
        }
    }
}

// ---------------- hidden transpose: h[b][k] -> quad-k hq[k/4][b][k%4] ---------
__global__ void k_transpose_h(const float* __restrict__ h, float* __restrict__ hq) {
    int b = blockIdx.x;
    int k = threadIdx.x;
    hq[(k >> 2) * (BATCH * 4) + (b << 2) + (k & 3)] = h[b * HID + k];
}

// ---------------- persistent recurrence (one layer, 128 steps) ---------------
// W slice cached transposed: Wt[k][j] = Whh[j0+j][k] (j-pairs contiguous ->
// 64-bit operands for packed fma.rn.f32x2; halves FMA issue count).
__global__ __launch_bounds__(256)
void k_rnn_persist(const float* __restrict__ xw,    // [SEQ][32][1024]
                   const float* __restrict__ Whh,   // [1024][1024]
                   const float* __restrict__ bhh,   // [1024]
                   float* __restrict__ hT,          // [2][1024*32] quad-k ping-pong
                   float* __restrict__ y,           // [SEQ][32][1024]
                   int epoch_base) {
    __shared__ __align__(16) float Wt[HID][8];      // 32 KB, [k][j]
    __shared__ float red[8][8][32];
    __shared__ float bias_s[8];
    const int tid  = threadIdx.x;
    const int w    = tid >> 5;
    const int lane = tid & 31;
    const int j0   = blockIdx.x * 8;

    {   // load W slice transposed: 2048 float4 reads, scatter to Wt[k][j]
        #pragma unroll
        for (int i = 0; i < 8; i++) {
            int s = tid + i * 256;          // 0..2047 float4 slots
            int j = s >> 8;                 // 0..7
            int kk = (s & 255) << 2;        // 0..1020
            float4 v = *reinterpret_cast<const float4*>(&Whh[(size_t)(j0 + j) * HID + kk]);
            Wt[kk + 0][j] = v.x; Wt[kk + 1][j] = v.y;
            Wt[kk + 2][j] = v.z; Wt[kk + 3][j] = v.w;
        }
        if (tid < 8) bias_s[tid] = bhh[j0 + tid];
    }
    __syncthreads();

    const int kbase = w * 128;

    for (int t = 0; t < SEQ; t++) {
        const float* hp = hT + (size_t)(t & 1) * (HID * BATCH);
        float*       hn = hT + (size_t)((t + 1) & 1) * (HID * BATCH);

        unsigned long long acc2[4] = {0ull, 0ull, 0ull, 0ull};   // (0.f,0.f) pairs

        #pragma unroll 4
        for (int kg = 0; kg < 128; kg += 8) {
            int q = (kbase + kg) >> 2;
            float4 h0 = __ldcg(reinterpret_cast<const float4*>(&hp[q * 128 + (lane << 2)]));
            float4 h1 = __ldcg(reinterpret_cast<const float4*>(&hp[(q + 1) * 128 + (lane << 2)]));
            float hv[8] = {h0.x, h0.y, h0.z, h0.w, h1.x, h1.y, h1.z, h1.w};
            #pragma unroll
            for (int u = 0; u < 8; u++) {
                const int k = kbase + kg + u;
                unsigned long long hh;
                asm("mov.b64 %0, {%1, %1};" : "=l"(hh) : "r"(__float_as_uint(hv[u])));
                ulonglong2 w01 = *reinterpret_cast<const ulonglong2*>(&Wt[k][0]);
                ulonglong2 w23 = *reinterpret_cast<const ulonglong2*>(&Wt[k][4]);
                FMA2(acc2[0], hh, w01.x);
                FMA2(acc2[1], hh, w01.y);
                FMA2(acc2[2], hh, w23.x);
                FMA2(acc2[3], hh, w23.y);
            }
        }

        #pragma unroll
        for (int p = 0; p < 4; p++) {
            uint32_t u0, u1;
            asm("mov.b64 {%0, %1}, %2;" : "=r"(u0), "=r"(u1) : "l"(acc2[p]));
            red[w][2 * p    ][lane] = __uint_as_float(u0);
            red[w][2 * p + 1][lane] = __uint_as_float(u1);
        }
        __syncthreads();

        {
            const int j = tid >> 5, b = tid & 31;
            float s = red[0][j][b] + red[1][j][b] + red[2][j][b] + red[3][j][b]
                    + red[4][j][b] + red[5][j][b] + red[6][j][b] + red[7][j][b];
            s += __ldg(&xw[(size_t)t * (BATCH * HID) + b * HID + (j0 + j)]) + bias_s[j];
            float v = tanhf(s);
            int jj = j0 + j;
            hn[(jj >> 2) * 128 + (b << 2) + (jj & 3)] = v;
            y[(size_t)t * (BATCH * HID) + b * HID + jj] = v;
        }
        grid_sync((unsigned)(epoch_base + t + 1));
    }
}

// ---------------- in-place row log_softmax ------------------------------------
__global__ void k_logsoftmax(float* __restrict__ logits) {
    extern __shared__ float row[];
    __shared__ float red[33];
    const int tid = threadIdx.x;
    float* p = logits + (size_t)blockIdx.x * VOC;

    float mx = -INFINITY;
    for (int i = tid; i < VOC / 4; i += 256) {
        float4 v = reinterpret_cast<const float4*>(p)[i];
        reinterpret_cast<float4*>(row)[i] = v;
        mx = fmaxf(mx, fmaxf(fmaxf(v.x, v.y), fmaxf(v.z, v.w)));
    }
    #pragma unroll
    for (int o = 16; o; o >>= 1) mx = fmaxf(mx, __shfl_xor_sync(0xffffffffu, mx, o));
    if ((tid & 31) == 0) red[tid >> 5] = mx;
    __syncthreads();
    if (tid < 32) {
        float m = (tid < 8) ? red[tid] : -INFINITY;
        #pragma unroll
        for (int o = 4; o; o >>= 1) m = fmaxf(m, __shfl_xor_sync(0xffffffffu, m, o));
        if (tid == 0) red[32] = m;
    }
    __syncthreads();
    mx = red[32];

    float s = 0.f;
    for (int i = tid; i < VOC; i += 256) s += __expf(row[i] - mx);
    #pragma unroll
    for (int o = 16; o; o >>= 1) s += __shfl_xor_sync(0xffffffffu, s, o);
    if ((tid & 31) == 0) red[tid >> 5] = s;
    __syncthreads();
    if (tid < 32) {
        float t2 = (tid < 8) ? red[tid] : 0.f;
        #pragma unroll
        for (int o = 4; o; o >>= 1) t2 += __shfl_xor_sync(0xffffffffu, t2, o);
        if (tid == 0) red[32] = t2;
    }
    __syncthreads();
    float lse = mx + logf(red[32]);

    for (int i = tid; i < VOC / 4; i += 256) {
        float4 v = reinterpret_cast<float4*>(row)[i];
        float4 o = make_float4(v.x - lse, v.y - lse, v.z - lse, v.w - lse);
        reinterpret_cast<float4*>(p)[i] = o;
    }
}

// ---------------- final hidden copy -------------------------------------------
__global__ void k_copy_hidden(const float* __restrict__ y0, const float* __restrict__ y1,
                              float* __restrict__ outh) {
    int i = blockIdx.x * 256 + threadIdx.x;
    outh[i]               = y0[(SEQ - 1) * BATCH * HID + i];
    outh[BATCH * HID + i] = y1[(SEQ - 1) * BATCH * HID + i];
}

// ---------------- launch --------------------------------------------------------
extern "C" void kernel_launch(void* const* d_in, const int* in_sizes, int n_in,
                              void* d_out, int out_size) {
    const int*   input_x = (const int*)  d_in[0];
    const float* hidden  = (const float*)d_in[1];
    const float* emb     = (const float*)d_in[2];
    const float* W_ih    = (const float*)d_in[3];
    const float* W_hh    = (const float*)d_in[4];
    const float* b_ih    = (const float*)d_in[5];
    const float* b_hh    = (const float*)d_in[6];
    const float* W_out   = (const float*)d_in[7];
    const float* b_out   = (const float*)d_in[8];
    float* out = (float*)d_out;

    static float *x = nullptr, *xw, *y0, *y1, *hT;
    if (!x) {
        cudaGetSymbolAddress((void**)&x,  g_x);
        cudaGetSymbolAddress((void**)&xw, g_xw);
        cudaGetSymbolAddress((void**)&y0, g_y0);
        cudaGetSymbolAddress((void**)&y1, g_y1);
        cudaGetSymbolAddress((void**)&hT, g_hT);
        cudaFuncSetAttribute(k_logsoftmax,
                             cudaFuncAttributeMaxDynamicSharedMemorySize, VOC * 4);
        cudaFuncSetAttribute(k_tf32gemm_bias,
                             cudaFuncAttributeMaxDynamicSharedMemorySize, GEMM_SMEM_BYTES);
    }

    dim3 gsmall(HID / BN, TB / BM);   // (4, 32)
    dim3 gbig(VOC / BN, TB / BM);     // (125, 32)

    // launch order arranged so launch #4 (profiled) is the tf32 GEMM
    k_bar_reset<<<1, 1>>>();                                         // 1
    k_gather<<<TB, 256>>>(input_x, emb, x);                          // 2
    k_transpose_h<<<BATCH, HID>>>(hidden, hT);                       // 3  (layer 0)
    k_tf32gemm_bias<<<gsmall, 512, GEMM_SMEM_BYTES>>>(               // 4  <- profiled
        x, W_ih, b_ih, xw, TB, HID, HID);
    k_rnn_persist<<<NBLK, 256>>>(xw, W_hh, b_hh, hT, y0, 0);         // 5

    k_tf32gemm_bias<<<gsmall, 512, GEMM_SMEM_BYTES>>>(               // 6
        y0, W_ih + (size_t)HID * HID, b_ih + HID, xw, TB, HID, HID);
    k_transpose_h<<<BATCH, HID>>>(hidden + BATCH * HID, hT);         // 7  (layer 1)
    k_rnn_persist<<<NBLK, 256>>>(xw, W_hh + (size_t)HID * HID,       // 8
                                 b_hh + HID, hT, y1, SEQ);

    k_tf32gemm_bias<<<gbig, 512, GEMM_SMEM_BYTES>>>(                 // 9
        y1, W_out, b_out, out, TB, VOC, HID);
    k_logsoftmax<<<TB, 256, VOC * 4>>>(out);                         // 10

    long long hid_off = (long long)TB * VOC;
    if ((long long)out_size >= hid_off + 2LL * BATCH * HID) {
        k_copy_hidden<<<BATCH * HID / 256, 256>>>(y0, y1, out + hid_off);  // 11
    }
}